// round 15
// baseline (speedup 1.0000x reference)
#include <cuda_runtime.h>
#include <cuda_fp16.h>
#include <cstdint>

#define BATCH 4
#define SEQ   4096
#define CH    1024
#define HS    64

__device__ __half g_q[BATCH*SEQ*HS];
__device__ __half g_k[BATCH*SEQ*HS];
__device__ __half g_v[BATCH*SEQ*HS];
__device__ __half g_wt[3*HS*CH];             // W transposed: [n=192][k=1024] fp16
__device__ float  g_Opart[BATCH*SEQ*HS];     // attention partial O (summed via RED)
__device__ float  g_lpart[BATCH*SEQ];        // attention partial l
__device__ int    g_cnt[BATCH*32];           // per-qtile contributor counters

// ---------------------------------------------------------------- primitives
__device__ __forceinline__ uint32_t smem_u32(const void* p){
    uint32_t a;
    asm("{ .reg .u64 t; cvta.to.shared.u64 t, %1; cvt.u32.u64 %0, t; }":"=r"(a):"l"(p));
    return a;
}
__device__ __forceinline__ float ex2f(float x){
    float y; asm("ex2.approx.ftz.f32 %0, %1;" : "=f"(y) : "f"(x)); return y;
}
__device__ __forceinline__ uint32_t packh2(float lo, float hi){
    uint32_t u;
    asm("cvt.rn.f16x2.f32 %0, %2, %1;" : "=r"(u) : "f"(lo), "f"(hi));
    return u;
}
__device__ __forceinline__ void mma16(float* d, const uint32_t* a, const uint32_t* b){
    asm volatile("mma.sync.aligned.m16n8k16.row.col.f32.f16.f16.f32 "
        "{%0,%1,%2,%3}, {%4,%5,%6,%7}, {%8,%9}, {%0,%1,%2,%3};"
        : "+f"(d[0]), "+f"(d[1]), "+f"(d[2]), "+f"(d[3])
        : "r"(a[0]), "r"(a[1]), "r"(a[2]), "r"(a[3]), "r"(b[0]), "r"(b[1]));
}
#define LDSM4(r0,r1,r2,r3,addr)                                              \
    asm volatile("ldmatrix.sync.aligned.m8n8.x4.shared.b16 {%0,%1,%2,%3}, [%4];" \
        : "=r"(r0), "=r"(r1), "=r"(r2), "=r"(r3) : "r"(addr))
#define LDSM4T(r0,r1,r2,r3,addr)                                             \
    asm volatile("ldmatrix.sync.aligned.m8n8.x4.trans.shared.b16 {%0,%1,%2,%3}, [%4];" \
        : "=r"(r0), "=r"(r1), "=r"(r2), "=r"(r3) : "r"(addr))
#define CPA(dst, src) asm volatile("cp.async.cg.shared.global [%0], [%1], 16;" \
        :: "r"(dst), "l"(src) : "memory")
#define CPA_COMMIT() asm volatile("cp.async.commit_group;" ::: "memory")
#define CPA_WAIT0()  asm volatile("cp.async.wait_group 0;" ::: "memory")

#define BARG(id) asm volatile("bar.sync %0, 256;" :: "r"(id) : "memory")
#define C_EXP 0.18033688011112042f   // (1/8) * log2(e)

#define KSTR 144    // fp16 tile row stride (bytes) = 9*16 (ldmatrix-aligned)
#define PSTR 80     // P buffer row stride = 5*16
#define XSTG 272    // f32 staging row stride (bytes) = 17*16

// ------------------------------------------------------------ prep kernel
__global__ __launch_bounds__(512) void prep(const float* __restrict__ Wq,
                                            const float* __restrict__ Wk,
                                            const float* __restrict__ Wv){
    int idx = blockIdx.x * 512 + threadIdx.x;        // grid 520*512 = 266240
    if (idx < 262144) ((float4*)g_Opart)[idx] = make_float4(0.f,0.f,0.f,0.f);
    else ((float4*)g_lpart)[idx - 262144] = make_float4(0.f,0.f,0.f,0.f);
    if (idx < BATCH*32) g_cnt[idx] = 0;
    if (idx < 3*65536) {
        int w = idx >> 16, rem = idx & 65535;
        int k = rem >> 6, n = rem & 63;
        const float* W = (w == 0) ? Wq : (w == 1) ? Wk : Wv;
        g_wt[(size_t)(w*64 + n)*CH + k] = __float2half(W[rem]);
    }
}

// ---------------------------------------------------------------- QKV kernel
// grid 128, block 512. cp.async double-buffered; f32 x staged and converted
// in-kernel. Each warp converts ITS OWN 16 A-rows -> only syncwarp needed
// after convert (single block barrier per panel, for W visibility).
#define QKV_BUF  (128*XSTG + 128*KSTR + 192*KSTR)
#define QKV_SMEM (2*QKV_BUF)
__global__ __launch_bounds__(512, 1) void qkv_tc(const float* __restrict__ x)
{
    extern __shared__ __align__(16) char sm[];
    const int tid = threadIdx.x, w = tid >> 5, ln = tid & 31;
    const int m = ln & 3, qr = ln >> 2;
    const int wh = w >> 3;
    const int wrow = (w & 7) * 16;
    const int row0 = blockIdx.x * 128;
    const uint32_t SB = smem_u32(sm);

    const int l7 = ln & 7, l3 = (ln >> 3) & 1, l4 = (ln >> 4) & 1;
    const uint32_t offA = (uint32_t)((l7 + l3*8)*KSTR + l4*16);
    const uint32_t offB = (uint32_t)(l7*KSTR + (ln >> 3)*16);

    const float* xp0 = x + (size_t)row0 * CH;

    #define QKV_FILL(c, p) do {                                              \
        uint32_t base = SB + (p)*QKV_BUF;                                    \
        const float* xp = xp0 + (c)*64;                                      \
        _Pragma("unroll")                                                    \
        for (int i = 0; i < 4; i++) {                                        \
            int idx = tid + i*512, r = idx >> 4, c16 = idx & 15;             \
            CPA(base + (uint32_t)(r*XSTG + c16*16), xp + (size_t)r*CH + c16*4);\
        }                                                                    \
        const __half* wp = g_wt + (c)*64;                                    \
        _Pragma("unroll")                                                    \
        for (int i = 0; i < 3; i++) {                                        \
            int idx = tid + i*512, n = idx >> 3, c8 = idx & 7;               \
            CPA(base + (uint32_t)(128*XSTG + 128*KSTR + n*KSTR + c8*16),     \
                wp + (size_t)n*CH + c8*8);                                   \
        }                                                                    \
        CPA_COMMIT();                                                        \
    } while (0)

    float o[12][4];
    #pragma unroll
    for (int i = 0; i < 12; i++) { o[i][0]=o[i][1]=o[i][2]=o[i][3]=0.f; }

    QKV_FILL(0, 0);

    // per-warp convert mapping: rows wrow..wrow+15, lane handles row wrow+(ln>>1),
    // half h = ln&1 (32 f32 each)
    const int cvr = wrow + (ln >> 1), cvh = ln & 1;

    #pragma unroll 1
    for (int c = 0; c < 16; c++) {
        const int p = c & 1;
        CPA_WAIT0();
        __syncthreads();                 // own-group done + W visible block-wide
        if (c < 15) QKV_FILL(c + 1, 1 - p);

        // convert this warp's 16 rows of staged f32 -> fp16 tile
        {
            const char* stg = sm + p*QKV_BUF + cvr*XSTG + cvh*128;
            char* xt = sm + p*QKV_BUF + 128*XSTG + cvr*KSTR + cvh*64;
            #pragma unroll
            for (int j = 0; j < 4; j++) {
                float4 f0 = *(const float4*)(stg + j*32);
                float4 f1 = *(const float4*)(stg + j*32 + 16);
                uint4 u = make_uint4(packh2(f0.x,f0.y), packh2(f0.z,f0.w),
                                     packh2(f1.x,f1.y), packh2(f1.z,f1.w));
                *(uint4*)(xt + j*16) = u;
            }
        }
        __syncwarp();

        const uint32_t XB  = SB + p*QKV_BUF + 128*XSTG;
        const uint32_t WBb = XB + 128*KSTR;
        #pragma unroll
        for (int ksh = 0; ksh < 2; ksh++) {
            uint32_t a[2][4];
            LDSM4(a[0][0], a[0][1], a[0][2], a[0][3],
                  XB + (uint32_t)(wrow*KSTR + ksh*64) + offA);
            LDSM4(a[1][0], a[1][1], a[1][2], a[1][3],
                  XB + (uint32_t)(wrow*KSTR + ksh*64 + 32) + offA);
            #pragma unroll
            for (int nt = 0; nt < 12; nt++) {
                uint32_t bf[4];
                LDSM4(bf[0], bf[1], bf[2], bf[3],
                      WBb + (uint32_t)((wh*96 + nt*8)*KSTR + ksh*64) + offB);
                mma16(o[nt], a[0], bf);
                mma16(o[nt], a[1], bf+2);
            }
        }
        __syncthreads();                 // all warps done with buffer p
    }
    __half* dsts[3] = {g_q, g_k, g_v};
    const int rg = row0 + wrow + qr;
    #pragma unroll
    for (int nt = 0; nt < 12; nt++) {
        int ntg = wh*96 + nt*8;
        __half* d = dsts[ntg >> 6];
        int col = (ntg & 63) + 2*m;
        *(__half2*)(d + (size_t)rg*HS + col) =
            __floats2half2_rn(o[nt][0], o[nt][1]);
        *(__half2*)(d + (size_t)(rg+8)*HS + col) =
            __floats2half2_rn(o[nt][2], o[nt][3]);
    }
}

// ----------------------------------------------------------- attention kernel
// Balanced flat schedule over 148 CTAs (split-K additive partials, RED flush).
// NEW: last contributing CTA per q-tile finalizes (divide + write out) —
// the unit->CTA partition is closed-form, so contributors are computable.
#define TILE_BYTES (2*128*KSTR)                 // K + V
#define QS_BYTES   (128*KSTR)
#define PS_BYTES   (16*PSTR)
#define ATT_SMEM   (QS_BYTES + 4*TILE_BYTES + 16*PS_BYTES)
#define NCTA   148
__device__ __forceinline__ int unit_owner(int u){
    return (u < 600) ? (u / 15) : ((u - 40) / 14);
}
__global__ __launch_bounds__(512, 1) void attn_tc(float* __restrict__ out)
{
    extern __shared__ __align__(16) char sm[];
    __shared__ int s_last;
    const int tid = threadIdx.x, w = tid >> 5, ln = tid & 31;
    const int m = ln & 3, qr = ln >> 2;
    const int g = w >> 3;
    const int gtid = tid & 255;
    const int wrow = (w & 7) * 16;
    char* Psw = sm + QS_BYTES + 4*TILE_BYTES + w*PS_BYTES;

    const int l7 = ln & 7, l3 = (ln >> 3) & 1, l4 = (ln >> 4) & 1;
    const uint32_t offA  = (uint32_t)((l7 + l3*8)*KSTR + l4*16);
    const uint32_t offKB = (uint32_t)(l7*KSTR + (ln >> 3)*16);
    const uint32_t offVB = (uint32_t)((l7 + l3*8)*KSTR + l4*16);
    const uint32_t offPA = (uint32_t)((l7 + l3*8)*PSTR + l4*16);
    const uint32_t SB = smem_u32(sm), PB = smem_u32(Psw);

    const int bi = blockIdx.x;
    int u  = bi*14 + (bi < 40 ? bi : 40);
    const int u1 = u + 14 + (bi < 40 ? 1 : 0);

    #define ATT_FILL(jt, p) do {                                             \
        uint32_t kb_ = SB + QS_BYTES + (uint32_t)((g*2 + (p))*TILE_BYTES);   \
        uint32_t vb_ = kb_ + 128*KSTR;                                       \
        const __half* kt_ = kg + (size_t)(jt)*128*HS;                        \
        const __half* vt_ = vg + (size_t)(jt)*128*HS;                        \
        _Pragma("unroll")                                                    \
        for (int i = 0; i < 4; i++) {                                        \
            int idx = gtid + i*256, r = idx >> 3, c8 = idx & 7;              \
            CPA(kb_ + (uint32_t)(r*KSTR + c8*16), kt_ + (size_t)r*HS + c8*8);\
            CPA(vb_ + (uint32_t)(r*KSTR + c8*16), vt_ + (size_t)r*HS + c8*8);\
        }                                                                    \
        CPA_COMMIT();                                                        \
    } while (0)

    #pragma unroll 1
    while (u < u1) {
        const int bb = u / 528;
        const int r  = u - bb * 528;
        int qt = (int)((sqrtf(8.f*r + 1.f) - 1.f) * 0.5f);
        while ((qt+1)*(qt+2)/2 <= r) qt++;
        while (qt*(qt+1)/2 > r) qt--;
        const int jt0 = r - qt*(qt+1)/2;
        int take = qt + 1 - jt0;
        if (take > u1 - u) take = u1 - u;

        const __half* qg = g_q + ((size_t)bb*SEQ + qt*128) * HS;
        const __half* kg = g_k + (size_t)bb*SEQ*HS;
        const __half* vg = g_v + (size_t)bb*SEQ*HS;

        __syncthreads();
        #pragma unroll
        for (int i = 0; i < 2; i++) {
            int idx = tid + i*512, rr = idx >> 3, c8 = idx & 7;
            *(uint4*)(sm + rr*KSTR + c8*16) = *(const uint4*)(qg + (size_t)rr*HS + c8*8);
        }
        __syncthreads();
        uint32_t q[4][4];
        {
            uint32_t qb = SB + (uint32_t)(wrow*KSTR) + offA;
            #pragma unroll
            for (int ks = 0; ks < 4; ks++)
                LDSM4(q[ks][0], q[ks][1], q[ks][2], q[ks][3], qb + ks*32);
        }

        float o[8][4];
        #pragma unroll
        for (int nt = 0; nt < 8; nt++) { o[nt][0]=o[nt][1]=o[nt][2]=o[nt][3]=0.f; }
        float l0 = 0.f, l1 = 0.f;

        const int myfirst = jt0 + g;
        const int myend   = jt0 + take;
        if (myfirst < myend) ATT_FILL(myfirst, 0);
        int p = 0;

        #pragma unroll 1
        for (int jt = myfirst; jt < myend; jt += 2) {
            CPA_WAIT0();
            BARG(g+1);
            if (jt + 2 < myend) ATT_FILL(jt + 2, 1 - p);

            const uint32_t KB = SB + QS_BYTES + (uint32_t)((g*2 + p)*TILE_BYTES);
            const uint32_t VB = KB + 128*KSTR;
            const bool diag = (jt == qt);
            const int rg0 = qt*128 + wrow + qr;
            const int rg1 = rg0 + 8;
            #pragma unroll 1
            for (int ch = 0; ch < 4; ch++) {
                float s[4][4];
                #pragma unroll
                for (int nt = 0; nt < 4; nt++)
                    { s[nt][0]=s[nt][1]=s[nt][2]=s[nt][3]=0.f; }
                #pragma unroll
                for (int nt = 0; nt < 4; nt++) {
                    const uint32_t krow = (uint32_t)((ch*32 + nt*8)*KSTR);
                    uint32_t bf[4];
                    LDSM4(bf[0], bf[1], bf[2], bf[3], KB + krow + offKB);
                    mma16(s[nt], q[0], bf);
                    mma16(s[nt], q[1], bf+2);
                    LDSM4(bf[0], bf[1], bf[2], bf[3], KB + krow + 64 + offKB);
                    mma16(s[nt], q[2], bf);
                    mma16(s[nt], q[3], bf+2);
                }
                #pragma unroll
                for (int nt = 0; nt < 4; nt++) {
                    const int kb = ch*32 + nt*8;
                    const int kg0 = jt*128 + kb + 2*m;
                    float p0 = ex2f(s[nt][0] * C_EXP);
                    float p1 = ex2f(s[nt][1] * C_EXP);
                    float p2 = ex2f(s[nt][2] * C_EXP);
                    float p3 = ex2f(s[nt][3] * C_EXP);
                    if (diag) {
                        if (kg0     > rg0) p0 = 0.f;
                        if (kg0 + 1 > rg0) p1 = 0.f;
                        if (kg0     > rg1) p2 = 0.f;
                        if (kg0 + 1 > rg1) p3 = 0.f;
                    }
                    l0 += p0 + p1;
                    l1 += p2 + p3;
                    *(uint32_t*)(Psw + qr*PSTR     + nt*16 + m*4) = packh2(p0, p1);
                    *(uint32_t*)(Psw + (qr+8)*PSTR + nt*16 + m*4) = packh2(p2, p3);
                }
                __syncwarp();
                #pragma unroll
                for (int kst = 0; kst < 2; kst++) {
                    uint32_t a[4];
                    LDSM4(a[0], a[1], a[2], a[3], PB + (uint32_t)(kst*32) + offPA);
                    const uint32_t vrow = (uint32_t)((ch*32 + kst*16)*KSTR);
                    #pragma unroll
                    for (int np = 0; np < 4; np++) {
                        uint32_t vb[4];
                        LDSM4T(vb[0], vb[1], vb[2], vb[3],
                               VB + vrow + (uint32_t)(np*32) + offVB);
                        mma16(o[2*np],   a, vb);
                        mma16(o[2*np+1], a, vb+2);
                    }
                }
                __syncwarp();
            }
            BARG(g+1);
            p ^= 1;
        }

        // flush partial (O, l) for this segment via RED adds
        if (myfirst < myend) {
            l0 += __shfl_xor_sync(0xffffffffu, l0, 1);
            l0 += __shfl_xor_sync(0xffffffffu, l0, 2);
            l1 += __shfl_xor_sync(0xffffffffu, l1, 1);
            l1 += __shfl_xor_sync(0xffffffffu, l1, 2);
            float* Ob = g_Opart + ((size_t)(bb*32 + qt)*128) * 64;
            const int r0 = wrow + qr, r1 = r0 + 8;
            #pragma unroll
            for (int nt = 0; nt < 8; nt++) {
                int col = nt*8 + 2*m;
                atomicAdd(&Ob[r0*64 + col],     o[nt][0]);
                atomicAdd(&Ob[r0*64 + col + 1], o[nt][1]);
                atomicAdd(&Ob[r1*64 + col],     o[nt][2]);
                atomicAdd(&Ob[r1*64 + col + 1], o[nt][3]);
            }
            if (m == 0) {
                atomicAdd(&g_lpart[(bb*32 + qt)*128 + r0], l0);
                atomicAdd(&g_lpart[(bb*32 + qt)*128 + r1], l1);
            }
        }

        // last-contributor finalize for this q-tile
        __threadfence();
        __syncthreads();                       // both groups' REDs issued+fenced
        if (tid == 0) {
            const int T = bb*528 + qt*(qt+1)/2;
            const int contrib = unit_owner(T + qt) - unit_owner(T) + 1;
            int old = atomicAdd(&g_cnt[bb*32 + qt], 1);
            s_last = (old == contrib - 1);
        }
        __syncthreads();
        if (s_last) {
            const float* Ob = g_Opart + ((size_t)(bb*32 + qt)*128) * 64;
            const float* lb = g_lpart + (bb*32 + qt)*128;
            float* dst = out + ((size_t)bb*SEQ + qt*128) * 64;
            #pragma unroll
            for (int i = 0; i < 4; i++) {
                int f = tid + i*512;           // float4 index within tile (2048)
                float4 ov = __ldcg((const float4*)Ob + f);
                float inv = 1.f / __ldcg(lb + (f >> 4));
                ((float4*)dst)[f] = make_float4(ov.x*inv, ov.y*inv, ov.z*inv, ov.w*inv);
            }
        }
        u += take;
    }
}

// ---------------------------------------------------------------------------
extern "C" void kernel_launch(void* const* d_in, const int* in_sizes, int n_in,
                              void* d_out, int out_size)
{
    const float* x  = (const float*)d_in[0];
    const float* Wq = (const float*)d_in[1];
    const float* Wk = (const float*)d_in[2];
    const float* Wv = (const float*)d_in[3];
    float* out = (float*)d_out;

    cudaFuncSetAttribute(qkv_tc,  cudaFuncAttributeMaxDynamicSharedMemorySize, QKV_SMEM);
    cudaFuncSetAttribute(attn_tc, cudaFuncAttributeMaxDynamicSharedMemorySize, ATT_SMEM);

    prep<<<520, 512>>>(Wq, Wk, Wv);
    qkv_tc<<<128, 512, QKV_SMEM>>>(x);
    attn_tc<<<NCTA, 512, ATT_SMEM>>>(out);
}

// round 16
// speedup vs baseline: 1.3883x; 1.3883x over previous
#include <cuda_runtime.h>
#include <cuda_fp16.h>
#include <cstdint>

#define BATCH 4
#define SEQ   4096
#define CH    1024
#define HS    64

__device__ __half g_q[BATCH*SEQ*HS];
__device__ __half g_k[BATCH*SEQ*HS];
__device__ __half g_v[BATCH*SEQ*HS];
__device__ __half g_wt[3*HS*CH];             // W transposed: [n=192][k=1024] fp16
__device__ float  g_Opart[BATCH*SEQ*HS];     // attention partial O (summed via RED)
__device__ float  g_lpart[BATCH*SEQ];        // attention partial l

// ---------------------------------------------------------------- primitives
__device__ __forceinline__ uint32_t smem_u32(const void* p){
    uint32_t a;
    asm("{ .reg .u64 t; cvta.to.shared.u64 t, %1; cvt.u32.u64 %0, t; }":"=r"(a):"l"(p));
    return a;
}
__device__ __forceinline__ float ex2f(float x){
    float y; asm("ex2.approx.ftz.f32 %0, %1;" : "=f"(y) : "f"(x)); return y;
}
__device__ __forceinline__ uint32_t packh2(float lo, float hi){
    uint32_t u;
    asm("cvt.rn.f16x2.f32 %0, %2, %1;" : "=r"(u) : "f"(lo), "f"(hi));
    return u;
}
__device__ __forceinline__ void mma16(float* d, const uint32_t* a, const uint32_t* b){
    asm volatile("mma.sync.aligned.m16n8k16.row.col.f32.f16.f16.f32 "
        "{%0,%1,%2,%3}, {%4,%5,%6,%7}, {%8,%9}, {%0,%1,%2,%3};"
        : "+f"(d[0]), "+f"(d[1]), "+f"(d[2]), "+f"(d[3])
        : "r"(a[0]), "r"(a[1]), "r"(a[2]), "r"(a[3]), "r"(b[0]), "r"(b[1]));
}
#define LDSM4(r0,r1,r2,r3,addr)                                              \
    asm volatile("ldmatrix.sync.aligned.m8n8.x4.shared.b16 {%0,%1,%2,%3}, [%4];" \
        : "=r"(r0), "=r"(r1), "=r"(r2), "=r"(r3) : "r"(addr))
#define LDSM4T(r0,r1,r2,r3,addr)                                             \
    asm volatile("ldmatrix.sync.aligned.m8n8.x4.trans.shared.b16 {%0,%1,%2,%3}, [%4];" \
        : "=r"(r0), "=r"(r1), "=r"(r2), "=r"(r3) : "r"(addr))
#define CPA(dst, src) asm volatile("cp.async.cg.shared.global [%0], [%1], 16;" \
        :: "r"(dst), "l"(src) : "memory")
#define CPA_COMMIT() asm volatile("cp.async.commit_group;" ::: "memory")
#define CPA_WAIT0()  asm volatile("cp.async.wait_group 0;" ::: "memory")

#define BARG(id) asm volatile("bar.sync %0, 256;" :: "r"(id) : "memory")
#define C_EXP 0.18033688011112042f   // (1/8) * log2(e)

#define KSTR 144    // fp16 tile row stride (bytes) = 9*16 (ldmatrix-aligned)
#define PSTR 80     // P buffer row stride = 5*16
#define XSTG 272    // f32 staging row stride (bytes) = 17*16

// ------------------------------------------------------------ prep kernel
__global__ __launch_bounds__(512) void prep(const float* __restrict__ Wq,
                                            const float* __restrict__ Wk,
                                            const float* __restrict__ Wv){
    int idx = blockIdx.x * 512 + threadIdx.x;        // grid 520*512 = 266240
    if (idx < 262144) ((float4*)g_Opart)[idx] = make_float4(0.f,0.f,0.f,0.f);
    else ((float4*)g_lpart)[idx - 262144] = make_float4(0.f,0.f,0.f,0.f);
    if (idx < 3*65536) {
        int w = idx >> 16, rem = idx & 65535;
        int k = rem >> 6, n = rem & 63;
        const float* W = (w == 0) ? Wq : (w == 1) ? Wk : Wv;
        g_wt[(size_t)(w*64 + n)*CH + k] = __float2half(W[rem]);
    }
}
__global__ __launch_bounds__(512) void attn_epi(float* __restrict__ out){
    int i = blockIdx.x * 512 + threadIdx.x;          // 262144 float4
    float4 o = ((float4*)g_Opart)[i];
    float inv = 1.f / g_lpart[i >> 4];
    ((float4*)out)[i] = make_float4(o.x*inv, o.y*inv, o.z*inv, o.w*inv);
}

// ---------------------------------------------------------------- QKV kernel
// grid 256, block 256 (8 warps), 64 rows/CTA -> 2 CTAs/SM: cross-CTA overlap
// hides fill latency (round-13/14 qkv was latency-bound at 1 CTA/SM).
// cp.async double-buffered; f32 x staged + converted in-kernel.
#define QKV_BUF  (64*XSTG + 64*KSTR + 192*KSTR)
#define QKV_SMEM (2*QKV_BUF)
__global__ __launch_bounds__(256, 2) void qkv_tc(const float* __restrict__ x)
{
    extern __shared__ __align__(16) char sm[];
    const int tid = threadIdx.x, w = tid >> 5, ln = tid & 31;
    const int m = ln & 3, qr = ln >> 2;
    const int wh = w >> 2;          // n-half (0..1)
    const int wrow = (w & 3) * 16;  // warp's row base within 64
    const int row0 = blockIdx.x * 64;
    const uint32_t SB = smem_u32(sm);

    const int l7 = ln & 7, l3 = (ln >> 3) & 1, l4 = (ln >> 4) & 1;
    const uint32_t offA = (uint32_t)((l7 + l3*8)*KSTR + l4*16);
    const uint32_t offB = (uint32_t)(l7*KSTR + (ln >> 3)*16);

    const float* xp0 = x + (size_t)row0 * CH;

    #define QKV_FILL(c, p) do {                                              \
        uint32_t base = SB + (p)*QKV_BUF;                                    \
        const float* xp = xp0 + (c)*64;                                      \
        _Pragma("unroll")                                                    \
        for (int i = 0; i < 4; i++) {                                        \
            int idx = tid + i*256, r = idx >> 4, c16 = idx & 15;             \
            CPA(base + (uint32_t)(r*XSTG + c16*16), xp + (size_t)r*CH + c16*4);\
        }                                                                    \
        const __half* wp = g_wt + (c)*64;                                    \
        _Pragma("unroll")                                                    \
        for (int i = 0; i < 6; i++) {                                        \
            int idx = tid + i*256, n = idx >> 3, c8 = idx & 7;               \
            CPA(base + (uint32_t)(64*XSTG + 64*KSTR + n*KSTR + c8*16),       \
                wp + (size_t)n*CH + c8*8);                                   \
        }                                                                    \
        CPA_COMMIT();                                                        \
    } while (0)

    float o[12][4];
    #pragma unroll
    for (int i = 0; i < 12; i++) { o[i][0]=o[i][1]=o[i][2]=o[i][3]=0.f; }

    QKV_FILL(0, 0);

    const int cr = tid >> 2, cs = tid & 3;   // convert mapping: row (0..63), segment

    #pragma unroll 1
    for (int c = 0; c < 16; c++) {
        const int p = c & 1;
        CPA_WAIT0();
        __syncthreads();
        if (c < 15) QKV_FILL(c + 1, 1 - p);

        // convert staged f32 panel -> fp16 tile (block-spread, as round 14)
        {
            const char* stg = sm + p*QKV_BUF;
            char* xt = sm + p*QKV_BUF + 64*XSTG;
            float4 f0 = *(const float4*)(stg + cr*XSTG + cs*64);
            float4 f1 = *(const float4*)(stg + cr*XSTG + cs*64 + 16);
            float4 f2 = *(const float4*)(stg + cr*XSTG + cs*64 + 32);
            float4 f3 = *(const float4*)(stg + cr*XSTG + cs*64 + 48);
            uint4 u0 = make_uint4(packh2(f0.x,f0.y), packh2(f0.z,f0.w),
                                  packh2(f1.x,f1.y), packh2(f1.z,f1.w));
            uint4 u1 = make_uint4(packh2(f2.x,f2.y), packh2(f2.z,f2.w),
                                  packh2(f3.x,f3.y), packh2(f3.z,f3.w));
            *(uint4*)(xt + cr*KSTR + cs*32)      = u0;
            *(uint4*)(xt + cr*KSTR + cs*32 + 16) = u1;
        }
        __syncthreads();

        const uint32_t XB  = SB + p*QKV_BUF + 64*XSTG;
        const uint32_t WBb = XB + 64*KSTR;
        #pragma unroll
        for (int ksh = 0; ksh < 2; ksh++) {
            uint32_t a[2][4];
            LDSM4(a[0][0], a[0][1], a[0][2], a[0][3],
                  XB + (uint32_t)(wrow*KSTR + ksh*64) + offA);
            LDSM4(a[1][0], a[1][1], a[1][2], a[1][3],
                  XB + (uint32_t)(wrow*KSTR + ksh*64 + 32) + offA);
            #pragma unroll
            for (int nt = 0; nt < 12; nt++) {
                uint32_t bf[4];
                LDSM4(bf[0], bf[1], bf[2], bf[3],
                      WBb + (uint32_t)((wh*96 + nt*8)*KSTR + ksh*64) + offB);
                mma16(o[nt], a[0], bf);
                mma16(o[nt], a[1], bf+2);
            }
        }
    }
    __half* dsts[3] = {g_q, g_k, g_v};
    const int rg = row0 + wrow + qr;
    #pragma unroll
    for (int nt = 0; nt < 12; nt++) {
        int ntg = wh*96 + nt*8;
        __half* d = dsts[ntg >> 6];
        int col = (ntg & 63) + 2*m;
        *(__half2*)(d + (size_t)rg*HS + col) =
            __floats2half2_rn(o[nt][0], o[nt][1]);
        *(__half2*)(d + (size_t)(rg+8)*HS + col) =
            __floats2half2_rn(o[nt][2], o[nt][3]);
    }
}

// ----------------------------------------------------------- attention kernel
// (identical to round-14 97.0us version) Balanced flat schedule over 148 CTAs;
// split-K additive partials flushed via RED; cp.async double-buffered K+V.
#define TILE_BYTES (2*128*KSTR)                 // K + V
#define QS_BYTES   (128*KSTR)
#define PS_BYTES   (16*PSTR)
#define ATT_SMEM   (QS_BYTES + 4*TILE_BYTES + 16*PS_BYTES)
#define NCTA   148
__global__ __launch_bounds__(512, 1) void attn_tc()
{
    extern __shared__ __align__(16) char sm[];
    const int tid = threadIdx.x, w = tid >> 5, ln = tid & 31;
    const int m = ln & 3, qr = ln >> 2;
    const int g = w >> 3;
    const int gtid = tid & 255;
    const int wrow = (w & 7) * 16;
    char* Psw = sm + QS_BYTES + 4*TILE_BYTES + w*PS_BYTES;

    const int l7 = ln & 7, l3 = (ln >> 3) & 1, l4 = (ln >> 4) & 1;
    const uint32_t offA  = (uint32_t)((l7 + l3*8)*KSTR + l4*16);
    const uint32_t offKB = (uint32_t)(l7*KSTR + (ln >> 3)*16);
    const uint32_t offVB = (uint32_t)((l7 + l3*8)*KSTR + l4*16);
    const uint32_t offPA = (uint32_t)((l7 + l3*8)*PSTR + l4*16);
    const uint32_t SB = smem_u32(sm), PB = smem_u32(Psw);

    const int bi = blockIdx.x;
    int u  = bi*14 + (bi < 40 ? bi : 40);
    const int u1 = u + 14 + (bi < 40 ? 1 : 0);

    #define ATT_FILL(jt, p) do {                                             \
        uint32_t kb_ = SB + QS_BYTES + (uint32_t)((g*2 + (p))*TILE_BYTES);   \
        uint32_t vb_ = kb_ + 128*KSTR;                                       \
        const __half* kt_ = kg + (size_t)(jt)*128*HS;                        \
        const __half* vt_ = vg + (size_t)(jt)*128*HS;                        \
        _Pragma("unroll")                                                    \
        for (int i = 0; i < 4; i++) {                                        \
            int idx = gtid + i*256, r = idx >> 3, c8 = idx & 7;              \
            CPA(kb_ + (uint32_t)(r*KSTR + c8*16), kt_ + (size_t)r*HS + c8*8);\
            CPA(vb_ + (uint32_t)(r*KSTR + c8*16), vt_ + (size_t)r*HS + c8*8);\
        }                                                                    \
        CPA_COMMIT();                                                        \
    } while (0)

    #pragma unroll 1
    while (u < u1) {
        const int bb = u / 528;
        const int r  = u - bb * 528;
        int qt = (int)((sqrtf(8.f*r + 1.f) - 1.f) * 0.5f);
        while ((qt+1)*(qt+2)/2 <= r) qt++;
        while (qt*(qt+1)/2 > r) qt--;
        const int jt0 = r - qt*(qt+1)/2;
        int take = qt + 1 - jt0;
        if (take > u1 - u) take = u1 - u;

        const __half* qg = g_q + ((size_t)bb*SEQ + qt*128) * HS;
        const __half* kg = g_k + (size_t)bb*SEQ*HS;
        const __half* vg = g_v + (size_t)bb*SEQ*HS;

        __syncthreads();
        #pragma unroll
        for (int i = 0; i < 2; i++) {
            int idx = tid + i*512, rr = idx >> 3, c8 = idx & 7;
            *(uint4*)(sm + rr*KSTR + c8*16) = *(const uint4*)(qg + (size_t)rr*HS + c8*8);
        }
        __syncthreads();
        uint32_t q[4][4];
        {
            uint32_t qb = SB + (uint32_t)(wrow*KSTR) + offA;
            #pragma unroll
            for (int ks = 0; ks < 4; ks++)
                LDSM4(q[ks][0], q[ks][1], q[ks][2], q[ks][3], qb + ks*32);
        }

        float o[8][4];
        #pragma unroll
        for (int nt = 0; nt < 8; nt++) { o[nt][0]=o[nt][1]=o[nt][2]=o[nt][3]=0.f; }
        float l0 = 0.f, l1 = 0.f;

        const int myfirst = jt0 + g;
        const int myend   = jt0 + take;
        if (myfirst < myend) ATT_FILL(myfirst, 0);
        int p = 0;

        #pragma unroll 1
        for (int jt = myfirst; jt < myend; jt += 2) {
            CPA_WAIT0();
            BARG(g+1);
            if (jt + 2 < myend) ATT_FILL(jt + 2, 1 - p);

            const uint32_t KB = SB + QS_BYTES + (uint32_t)((g*2 + p)*TILE_BYTES);
            const uint32_t VB = KB + 128*KSTR;
            const bool diag = (jt == qt);
            const int rg0 = qt*128 + wrow + qr;
            const int rg1 = rg0 + 8;
            #pragma unroll 1
            for (int ch = 0; ch < 4; ch++) {
                float s[4][4];
                #pragma unroll
                for (int nt = 0; nt < 4; nt++)
                    { s[nt][0]=s[nt][1]=s[nt][2]=s[nt][3]=0.f; }
                #pragma unroll
                for (int nt = 0; nt < 4; nt++) {
                    const uint32_t krow = (uint32_t)((ch*32 + nt*8)*KSTR);
                    uint32_t bf[4];
                    LDSM4(bf[0], bf[1], bf[2], bf[3], KB + krow + offKB);
                    mma16(s[nt], q[0], bf);
                    mma16(s[nt], q[1], bf+2);
                    LDSM4(bf[0], bf[1], bf[2], bf[3], KB + krow + 64 + offKB);
                    mma16(s[nt], q[2], bf);
                    mma16(s[nt], q[3], bf+2);
                }
                #pragma unroll
                for (int nt = 0; nt < 4; nt++) {
                    const int kb = ch*32 + nt*8;
                    const int kg0 = jt*128 + kb + 2*m;
                    float p0 = ex2f(s[nt][0] * C_EXP);
                    float p1 = ex2f(s[nt][1] * C_EXP);
                    float p2 = ex2f(s[nt][2] * C_EXP);
                    float p3 = ex2f(s[nt][3] * C_EXP);
                    if (diag) {
                        if (kg0     > rg0) p0 = 0.f;
                        if (kg0 + 1 > rg0) p1 = 0.f;
                        if (kg0     > rg1) p2 = 0.f;
                        if (kg0 + 1 > rg1) p3 = 0.f;
                    }
                    l0 += p0 + p1;
                    l1 += p2 + p3;
                    *(uint32_t*)(Psw + qr*PSTR     + nt*16 + m*4) = packh2(p0, p1);
                    *(uint32_t*)(Psw + (qr+8)*PSTR + nt*16 + m*4) = packh2(p2, p3);
                }
                __syncwarp();
                #pragma unroll
                for (int kst = 0; kst < 2; kst++) {
                    uint32_t a[4];
                    LDSM4(a[0], a[1], a[2], a[3], PB + (uint32_t)(kst*32) + offPA);
                    const uint32_t vrow = (uint32_t)((ch*32 + kst*16)*KSTR);
                    #pragma unroll
                    for (int np = 0; np < 4; np++) {
                        uint32_t vb[4];
                        LDSM4T(vb[0], vb[1], vb[2], vb[3],
                               VB + vrow + (uint32_t)(np*32) + offVB);
                        mma16(o[2*np],   a, vb);
                        mma16(o[2*np+1], a, vb+2);
                    }
                }
                __syncwarp();
            }
            BARG(g+1);
            p ^= 1;
        }

        if (myfirst < myend) {
            l0 += __shfl_xor_sync(0xffffffffu, l0, 1);
            l0 += __shfl_xor_sync(0xffffffffu, l0, 2);
            l1 += __shfl_xor_sync(0xffffffffu, l1, 1);
            l1 += __shfl_xor_sync(0xffffffffu, l1, 2);
            float* Ob = g_Opart + ((size_t)(bb*32 + qt)*128) * 64;
            const int r0 = wrow + qr, r1 = r0 + 8;
            #pragma unroll
            for (int nt = 0; nt < 8; nt++) {
                int col = nt*8 + 2*m;
                atomicAdd(&Ob[r0*64 + col],     o[nt][0]);
                atomicAdd(&Ob[r0*64 + col + 1], o[nt][1]);
                atomicAdd(&Ob[r1*64 + col],     o[nt][2]);
                atomicAdd(&Ob[r1*64 + col + 1], o[nt][3]);
            }
            if (m == 0) {
                atomicAdd(&g_lpart[(bb*32 + qt)*128 + r0], l0);
                atomicAdd(&g_lpart[(bb*32 + qt)*128 + r1], l1);
            }
        }
        u += take;
    }
}

// ---------------------------------------------------------------------------
extern "C" void kernel_launch(void* const* d_in, const int* in_sizes, int n_in,
                              void* d_out, int out_size)
{
    const float* x  = (const float*)d_in[0];
    const float* Wq = (const float*)d_in[1];
    const float* Wk = (const float*)d_in[2];
    const float* Wv = (const float*)d_in[3];
    float* out = (float*)d_out;

    cudaFuncSetAttribute(qkv_tc,  cudaFuncAttributeMaxDynamicSharedMemorySize, QKV_SMEM);
    cudaFuncSetAttribute(attn_tc, cudaFuncAttributeMaxDynamicSharedMemorySize, ATT_SMEM);

    prep<<<520, 512>>>(Wq, Wk, Wv);
    qkv_tc<<<256, 256, QKV_SMEM>>>(x);
    attn_tc<<<NCTA, 512, ATT_SMEM>>>();
    attn_epi<<<512, 512>>>(out);
}